// round 3
// baseline (speedup 1.0000x reference)
#include <cuda_runtime.h>
#include <cstdint>

#define BB 256
#define TT 199
#define QQ 1000
#define VQ 250                        // float4 per row
#define NEL  ((size_t)BB * TT * QQ)   // 50,944,000

// Scratch (__device__ globals; zero-initialized at module load, and the
// final kernel resets them after use so every graph replay starts clean).
__device__ double g_bsum[BB];
__device__ int    g_bcnt[BB];

// One block (256 threads) per (b, t) row of 1000 floats = 250 float4.
__global__ __launch_bounds__(256) void row_kernel(
    const float* __restrict__ pred,    // (B, T, Q)
    const float* __restrict__ batch,   // (B, T+1, Q)
    float* __restrict__ out)
{
    const int t    = blockIdx.x;
    const int b    = blockIdx.y;
    const int tid  = threadIdx.x;
    const int lane = tid & 31;
    const int wid  = tid >> 5;
    const bool act = tid < VQ;

    const size_t row = (size_t)b * TT + t;
    const float4* __restrict__ gt4 =
        (const float4*)(batch + ((size_t)b * (TT + 1) + (t + 1)) * QQ);
    const float4* __restrict__ pr4 =
        (const float4*)(pred + row * QQ);

    __shared__ float s_p[QQ];
    __shared__ float s_g[QQ];
    __shared__ int   s_w[8];
    __shared__ float s_red[8];

    // ---- load gt (vectorized), block-wide any(g==1) ----
    float4 g = make_float4(0.f, 0.f, 0.f, 0.f);
    if (act) g = gt4[tid];
    int anyv = (g.x == 1.0f) | (g.y == 1.0f) | (g.z == 1.0f) | (g.w == 1.0f);
    unsigned wany = __ballot_sync(0xFFFFFFFFu, anyv);
    if (lane == 0) s_w[wid] = (wany != 0);
    __syncthreads();
    const int masked = s_w[0] | s_w[1] | s_w[2] | s_w[3] |
                       s_w[4] | s_w[5] | s_w[6] | s_w[7];
    const float fm = masked ? 1.0f : 0.0f;

    // ---- conditional pred load + bce ----
    float4 p = make_float4(0.f, 0.f, 0.f, 0.f);
    float lsum = 0.0f;   // +(g log p + (1-g) log(1-p)); bce = -lsum
    if (masked & (int)act) {
        p = pr4[tid];
        float lp, l1;
        lp = fmaxf(__logf(p.x), -100.0f); l1 = fmaxf(__logf(1.0f - p.x), -100.0f);
        lsum += g.x * lp + (1.0f - g.x) * l1;
        lp = fmaxf(__logf(p.y), -100.0f); l1 = fmaxf(__logf(1.0f - p.y), -100.0f);
        lsum += g.y * lp + (1.0f - g.y) * l1;
        lp = fmaxf(__logf(p.z), -100.0f); l1 = fmaxf(__logf(1.0f - p.z), -100.0f);
        lsum += g.z * lp + (1.0f - g.z) * l1;
        lp = fmaxf(__logf(p.w), -100.0f); l1 = fmaxf(__logf(1.0f - p.w), -100.0f);
        lsum += g.w * lp + (1.0f - g.w) * l1;
    }

    // ---- stage outputs in smem (p already 0 when unmasked; g needs *fm) ----
    if (act) {
        int q = tid * 4;
        s_p[q + 0] = p.x;      s_p[q + 1] = p.y;
        s_p[q + 2] = p.z;      s_p[q + 3] = p.w;
        s_g[q + 0] = g.x * fm; s_g[q + 1] = g.y * fm;
        s_g[q + 2] = g.z * fm; s_g[q + 3] = g.w * fm;
    }

    // warp-level reduce lsum while stores settle
    #pragma unroll
    for (int off = 16; off > 0; off >>= 1)
        lsum += __shfl_down_sync(0xFFFFFFFFu, lsum, off);
    if (lane == 0) s_red[wid] = lsum;
    __syncthreads();

    // ---- aligned vectorized stores (output region starts at +1 elem) ----
    float* __restrict__ outp = out + 1 + row * QQ;        // elem offset ≡ 1 (mod 4)
    float* __restrict__ outg = outp + NEL;
    if (tid < 249) {
        int q = 3 + tid * 4;                              // q = 3..995, +4 aligned
        float4 vp = make_float4(s_p[q], s_p[q+1], s_p[q+2], s_p[q+3]);
        float4 vg = make_float4(s_g[q], s_g[q+1], s_g[q+2], s_g[q+3]);
        *(float4*)(outp + q) = vp;                        // 16B aligned
        *(float4*)(outg + q) = vg;
    } else if (tid == 250) {
        outp[0] = s_p[0]; outp[1] = s_p[1]; outp[2] = s_p[2]; outp[999] = s_p[999];
    } else if (tid == 251) {
        outg[0] = s_g[0]; outg[1] = s_g[1]; outg[2] = s_g[2]; outg[999] = s_g[999];
    } else if (tid == 249) {
        // covered below by vec? no: tid runs 0..248 above; q max = 995 → 995..998.
        // element 999 handled by tids 250/251; nothing here.
    }

    // ---- finish reduction, per-batch atomics, row_mask ----
    if (tid < 32) {
        float v = (tid < 8) ? s_red[tid] : 0.0f;
        #pragma unroll
        for (int off = 4; off > 0; off >>= 1)
            v += __shfl_down_sync(0xFFFFFFFFu, v, off);
        if (tid == 0) {
            if (masked) {
                atomicAdd(&g_bsum[b], (double)(-v));
                atomicAdd(&g_bcnt[b], 1);
            }
            out[1 + 2 * NEL + row] = fm;
        }
    }
}

// Single final kernel: loss = sum_b bsum[b]/(cnt[b]*1000); then reset scratch.
__global__ __launch_bounds__(256) void final_kernel(float* __restrict__ out)
{
    __shared__ double s[BB];
    const int b = threadIdx.x;
    const int c = g_bcnt[b];
    s[b] = (c > 0) ? (g_bsum[b] / ((double)c * (double)QQ)) : 0.0;
    __syncthreads();
    #pragma unroll
    for (int off = BB / 2; off > 0; off >>= 1) {
        if (b < off) s[b] += s[b + off];
        __syncthreads();
    }
    if (b == 0) out[0] = (float)s[0];
    // reset for the next graph replay (deterministic: state returns to zero)
    g_bsum[b] = 0.0;
    g_bcnt[b] = 0;
}

extern "C" void kernel_launch(void* const* d_in, const int* in_sizes, int n_in,
                              void* d_out, int out_size) {
    const float* pred  = (const float*)d_in[0];
    const float* batch = (const float*)d_in[1];
    float* out = (float*)d_out;

    dim3 grid(TT, BB);
    row_kernel<<<grid, 256>>>(pred, batch, out);
    final_kernel<<<1, BB>>>(out);
}